// round 6
// baseline (speedup 1.0000x reference)
#include <cuda_runtime.h>
#include <math.h>

#define N_NODES 4096
#define IN_F    256
#define NH      4
#define HD      64
#define HID     256   // NH*HD

// ---------------- scratch (device globals; no allocs allowed) ----------------
__device__ float  g_h [N_NODES * HID];      // 4 MB: h = x @ W (fp32)
__device__ float  g_hq[N_NODES * HID];      // 4 MB: rna-tf32-rounded copy of h
__device__ float4 g_ipack[NH * N_NODES];    // (s1, exp(s1), exp(.2 s1), 0)
__device__ float4 g_jpack[NH * N_NODES];    // (s2, exp(s2), exp(.2 s2), 0)

__device__ __forceinline__ unsigned f2tf32(float f) {
    unsigned r;
    asm("cvt.rna.tf32.f32 %0, %1;" : "=r"(r) : "f"(f));
    return r;
}
__device__ __forceinline__ float f2tf32f(float f) { return __uint_as_float(f2tf32(f)); }

__device__ __forceinline__ void cpa16(void* dst, const void* src) {
    unsigned d = (unsigned)__cvta_generic_to_shared(dst);
    asm volatile("cp.async.ca.shared.global [%0], [%1], 16;\n" :: "r"(d), "l"(src));
}

// ---------------- kernel A: h = x @ W  (4096x256 @ 256x256) ----------------
__global__ __launch_bounds__(256) void gemm_hw(const float* __restrict__ A,
                                               const float* __restrict__ B,
                                               float* __restrict__ C,
                                               float* __restrict__ Cq) {
    __shared__ float As[16][65];
    __shared__ float Bs[16][65];
    int tx = threadIdx.x;
    int bm = blockIdx.x * 64;
    int bn = blockIdx.y * 64;
    int tm = (tx >> 4) * 4;
    int tn = (tx & 15) * 4;
    float acc[4][4] = {};
    for (int k0 = 0; k0 < 256; k0 += 16) {
        #pragma unroll
        for (int l = 0; l < 4; l++) {
            int idx = tx + l * 256;
            int m = idx >> 4, k = idx & 15;
            As[k][m] = A[(bm + m) * 256 + k0 + k];
        }
        {
            int k = tx >> 6, n = tx & 63;
            #pragma unroll
            for (int l = 0; l < 4; l++)
                Bs[k + l * 4][n] = B[(k0 + k + l * 4) * 256 + bn + n];
        }
        __syncthreads();
        #pragma unroll
        for (int k = 0; k < 16; k++) {
            float a[4], b[4];
            #pragma unroll
            for (int u = 0; u < 4; u++) a[u] = As[k][tm + u];
            #pragma unroll
            for (int v = 0; v < 4; v++) b[v] = Bs[k][tn + v];
            #pragma unroll
            for (int u = 0; u < 4; u++)
                #pragma unroll
                for (int v = 0; v < 4; v++) acc[u][v] += a[u] * b[v];
        }
        __syncthreads();
    }
    #pragma unroll
    for (int u = 0; u < 4; u++)
        #pragma unroll
        for (int v = 0; v < 4; v++) {
            size_t idx = (size_t)(bm + tm + u) * 256 + bn + tn + v;
            C [idx] = acc[u][v];
            Cq[idx] = f2tf32f(acc[u][v]);
        }
}

// ---------------- kernel B: scores + factorized exponential packs -----------
__global__ __launch_bounds__(256) void scores_kernel(const float* __restrict__ a1,
                                                     const float* __restrict__ a2) {
    int warp = (blockIdx.x * blockDim.x + threadIdx.x) >> 5;
    int lane = threadIdx.x & 31;
    if (warp >= N_NODES * NH) return;
    int node = warp >> 2, head = warp & 3;
    const float* hp = g_h + node * HID + head * HD;
    float v0 = hp[lane], v1 = hp[lane + 32];
    float s1 = v0 * a1[lane] + v1 * a1[lane + 32];
    float s2 = v0 * a2[lane] + v1 * a2[lane + 32];
    #pragma unroll
    for (int o = 16; o > 0; o >>= 1) {
        s1 += __shfl_xor_sync(0xffffffffu, s1, o);
        s2 += __shfl_xor_sync(0xffffffffu, s2, o);
    }
    if (lane == 0) {
        int idx = head * N_NODES + node;
        g_ipack[idx] = make_float4(s1, __expf(s1), __expf(0.2f * s1), 0.f);
        g_jpack[idx] = make_float4(s2, __expf(s2), __expf(0.2f * s2), 0.f);
    }
}

// ---------------- kernel C: pipelined flash-style tf32-MMA aggregation ------
#define TM  64
#define TJ  64
#define PST 68   // P smem stride (A-frag LDS conflict-free)
#define VST 72   // V smem stride (B-frag LDS conflict-free)

extern __shared__ float smem_dyn[];

__global__ __launch_bounds__(256, 2) void attn_mma(const int* __restrict__ adj,
                                                   float* __restrict__ out) {
    float*  Pb[2];
    float*  Vb[2];
    float4* Sb[2];
    Pb[0] = smem_dyn;
    Pb[1] = Pb[0] + TM * PST;
    Vb[0] = Pb[1] + TM * PST;
    Vb[1] = Vb[0] + TJ * VST;
    Sb[0] = (float4*)(Vb[1] + TJ * VST);
    Sb[1] = Sb[0] + TJ;
    float* dsh = (float*)(Sb[1] + TJ);

    int t    = threadIdx.x;
    int lane = t & 31;
    int warp = t >> 5;
    int i0   = blockIdx.x * TM;
    int head = blockIdx.y;

    int m = t >> 2;          // P-build / V-copy row
    int q = t & 3;           // P-build column quarter

    float4 ip = g_ipack[head * N_NODES + i0 + m];
    float s1i = ip.x, e1i = ip.y, e2i = ip.z;
    float dsum = 0.f;

    int mw = warp & 3;       // MMA row group
    int nw = warp >> 2;      // MMA col group
    float acc[4][4];
    #pragma unroll
    for (int a = 0; a < 4; a++)
        #pragma unroll
        for (int b = 0; b < 4; b++) acc[a][b] = 0.f;

    const int*    adjrow  = adj + (size_t)(i0 + m) * N_NODES;
    const float4* jp_base = g_jpack + head * N_NODES;
    const float*  vsrc    = g_hq + head * HD;

    // ---- prologue: stage chunk 0 (V, jpack) + jpack chunk 1 ----
    {
        if (t < TJ) {
            cpa16(&Sb[0][t], &jp_base[t]);
            cpa16(&Sb[1][t], &jp_base[TJ + t]);
        }
        const float* s = vsrc + (size_t)m * HID + q * 16;
        float*       d = Vb[0] + m * VST + q * 16;
        cpa16(d, s); cpa16(d + 4, s + 4); cpa16(d + 8, s + 8); cpa16(d + 12, s + 12);
        asm volatile("cp.async.commit_group;\n" ::: "memory");
        asm volatile("cp.async.wait_group 0;\n" ::: "memory");
        __syncthreads();
    }
    // build chunk 0 into P[0]
    {
        const int* ar = adjrow + q * 16;
        #pragma unroll
        for (int u = 0; u < 4; u++) {
            int jc = q * 16 + u * 4;
            int4 a = *(const int4*)(ar + u * 4);
            float4 j0 = Sb[0][jc], j1 = Sb[0][jc + 1], j2 = Sb[0][jc + 2], j3 = Sb[0][jc + 3];
            float w0 = (a.x > 0) ? ((s1i + j0.x > 0.f) ? e1i * j0.y : e2i * j0.z) : 0.f;
            float w1 = (a.y > 0) ? ((s1i + j1.x > 0.f) ? e1i * j1.y : e2i * j1.z) : 0.f;
            float w2 = (a.z > 0) ? ((s1i + j2.x > 0.f) ? e1i * j2.y : e2i * j2.z) : 0.f;
            float w3 = (a.w > 0) ? ((s1i + j3.x > 0.f) ? e1i * j3.y : e2i * j3.z) : 0.f;
            w0 = f2tf32f(w0); w1 = f2tf32f(w1); w2 = f2tf32f(w2); w3 = f2tf32f(w3);
            *(float4*)(Pb[0] + m * PST + jc) = make_float4(w0, w1, w2, w3);
            dsum += (w0 + w1) + (w2 + w3);
        }
    }
    __syncthreads();

    // ---- main pipelined loop ----
    for (int c = 0; c < N_NODES / TJ; c++) {
        int cb = c & 1, nb = cb ^ 1;

        // prefetch chunk c+1: adj -> regs, V -> smem[nb]; jpack chunk c+2 -> smem[cb]
        int4 av[4];
        if (c < 63) {
            const int* ar = adjrow + (c + 1) * TJ + q * 16;
            av[0] = *(const int4*)(ar);
            av[1] = *(const int4*)(ar + 4);
            av[2] = *(const int4*)(ar + 8);
            av[3] = *(const int4*)(ar + 12);
            const float* s = vsrc + (size_t)((c + 1) * TJ + m) * HID + q * 16;
            float*       d = Vb[nb] + m * VST + q * 16;
            cpa16(d, s); cpa16(d + 4, s + 4); cpa16(d + 8, s + 8); cpa16(d + 12, s + 12);
        }
        if (c < 62 && t < TJ)
            cpa16(&Sb[cb][t], &jp_base[(c + 2) * TJ + t]);
        asm volatile("cp.async.commit_group;\n" ::: "memory");

        // MMA on chunk c: acc += P[cb] @ V[cb]
        {
            const float* Pp = Pb[cb] + (mw * 16) * PST;
            const float* Vp = Vb[cb] + nw * 32;
            int r = lane >> 2, cc = lane & 3;
            #pragma unroll
            for (int k = 0; k < TJ; k += 8) {
                unsigned a0 = __float_as_uint(Pp[(r    ) * PST + k + cc    ]);
                unsigned a1 = __float_as_uint(Pp[(r + 8) * PST + k + cc    ]);
                unsigned a2 = __float_as_uint(Pp[(r    ) * PST + k + cc + 4]);
                unsigned a3 = __float_as_uint(Pp[(r + 8) * PST + k + cc + 4]);
                #pragma unroll
                for (int nt = 0; nt < 4; nt++) {
                    unsigned b0 = __float_as_uint(Vp[(k + cc    ) * VST + nt * 8 + r]);
                    unsigned b1 = __float_as_uint(Vp[(k + cc + 4) * VST + nt * 8 + r]);
                    asm volatile(
                        "mma.sync.aligned.m16n8k8.row.col.f32.tf32.tf32.f32 "
                        "{%0,%1,%2,%3}, {%4,%5,%6,%7}, {%8,%9}, {%0,%1,%2,%3};\n"
                        : "+f"(acc[nt][0]), "+f"(acc[nt][1]),
                          "+f"(acc[nt][2]), "+f"(acc[nt][3])
                        : "r"(a0), "r"(a1), "r"(a2), "r"(a3), "r"(b0), "r"(b1));
                }
            }
        }

        // build chunk c+1 into P[nb] from adj regs + Sb[nb]
        if (c < 63) {
            #pragma unroll
            for (int u = 0; u < 4; u++) {
                int jc = q * 16 + u * 4;
                int4 a = av[u];
                float4 j0 = Sb[nb][jc], j1 = Sb[nb][jc + 1], j2 = Sb[nb][jc + 2], j3 = Sb[nb][jc + 3];
                float w0 = (a.x > 0) ? ((s1i + j0.x > 0.f) ? e1i * j0.y : e2i * j0.z) : 0.f;
                float w1 = (a.y > 0) ? ((s1i + j1.x > 0.f) ? e1i * j1.y : e2i * j1.z) : 0.f;
                float w2 = (a.z > 0) ? ((s1i + j2.x > 0.f) ? e1i * j2.y : e2i * j2.z) : 0.f;
                float w3 = (a.w > 0) ? ((s1i + j3.x > 0.f) ? e1i * j3.y : e2i * j3.z) : 0.f;
                w0 = f2tf32f(w0); w1 = f2tf32f(w1); w2 = f2tf32f(w2); w3 = f2tf32f(w3);
                *(float4*)(Pb[nb] + m * PST + jc) = make_float4(w0, w1, w2, w3);
                dsum += (w0 + w1) + (w2 + w3);
            }
        }

        asm volatile("cp.async.wait_group 0;\n" ::: "memory");
        __syncthreads();
    }

    // ---- row denominators: reduce over column-quarters q (lane bits 0-1) ----
    dsum += __shfl_xor_sync(0xffffffffu, dsum, 1);
    dsum += __shfl_xor_sync(0xffffffffu, dsum, 2);
    if (q == 0) dsh[m] = dsum;
    __syncthreads();

    // ---- normalize + write ----
    int r = lane >> 2, c2 = (lane & 3) * 2;
    float inv0 = 1.f / dsh[mw * 16 + r];
    float inv1 = 1.f / dsh[mw * 16 + r + 8];
    #pragma unroll
    for (int nt = 0; nt < 4; nt++) {
        int col  = head * HD + nw * 32 + nt * 8 + c2;
        int row0 = i0 + mw * 16 + r;
        *(float2*)(out + (size_t)row0 * HID + col) =
            make_float2(acc[nt][0] * inv0, acc[nt][1] * inv0);
        *(float2*)(out + (size_t)(row0 + 8) * HID + col) =
            make_float2(acc[nt][2] * inv1, acc[nt][3] * inv1);
    }
}

// ---------------- launch ----------------
extern "C" void kernel_launch(void* const* d_in, const int* in_sizes, int n_in,
                              void* d_out, int out_size) {
    const float* x   = (const float*)d_in[0];   // [4096, 256]
    const int*   adj = (const int*)  d_in[1];   // [4096, 4096]
    const float* W   = (const float*)d_in[2];   // [256, 256]
    const float* a1  = (const float*)d_in[3];   // [64]
    const float* a2  = (const float*)d_in[4];   // [64]
    float* out = (float*)d_out;                 // [4096, 256]

    float *h_ptr, *hq_ptr;
    cudaGetSymbolAddress((void**)&h_ptr,  g_h);
    cudaGetSymbolAddress((void**)&hq_ptr, g_hq);

    dim3 ggrid(N_NODES / 64, HID / 64);
    gemm_hw<<<ggrid, 256>>>(x, W, h_ptr, hq_ptr);

    scores_kernel<<<(N_NODES * NH * 32) / 256, 256>>>(a1, a2);

    const int smem_bytes = (2 * TM * PST + 2 * TJ * VST) * 4 + 2 * TJ * 16 + TM * 4;
    cudaFuncSetAttribute(attn_mma, cudaFuncAttributeMaxDynamicSharedMemorySize, smem_bytes);
    attn_mma<<<dim3(N_NODES / TM, NH), 256, smem_bytes>>>(adj, out);
}

// round 8
// speedup vs baseline: 1.5640x; 1.5640x over previous
#include <cuda_runtime.h>
#include <math.h>

#define N_NODES 4096
#define IN_F    256
#define NH      4
#define HD      64
#define HID     256   // NH*HD
#define NSLICE  4
#define JSL     (N_NODES / NSLICE)   // 1024 j's per slice

// ---------------- scratch (device globals; no allocs allowed) ----------------
__device__ float g_h[N_NODES * HID];                 // 4 MB: h = x @ W
__device__ float g_s1[NH * N_NODES];
__device__ float g_s2[NH * N_NODES];
__device__ float g_e1i[NH * N_NODES];
__device__ float g_e2i[NH * N_NODES];
__device__ float g_e1j[NH * N_NODES];
__device__ float g_e2j[NH * N_NODES];
__device__ float g_num[NSLICE * N_NODES * HID];      // 16 MB numerator slices
__device__ float g_den[NSLICE * NH * N_NODES];       // denominator slices

__device__ __forceinline__ unsigned f2tf32(float f) {
    unsigned r;
    asm("cvt.rna.tf32.f32 %0, %1;" : "=r"(r) : "f"(f));
    return r;
}

// ---------------- kernel A: h = x @ W  (4096x256 @ 256x256) ----------------
__global__ __launch_bounds__(256) void gemm_hw(const float* __restrict__ A,
                                               const float* __restrict__ B,
                                               float* __restrict__ C) {
    __shared__ float As[16][65];
    __shared__ float Bs[16][65];
    int tx = threadIdx.x;
    int bm = blockIdx.x * 64;
    int bn = blockIdx.y * 64;
    int tm = (tx >> 4) * 4;
    int tn = (tx & 15) * 4;
    float acc[4][4] = {};
    for (int k0 = 0; k0 < 256; k0 += 16) {
        #pragma unroll
        for (int l = 0; l < 4; l++) {
            int idx = tx + l * 256;
            int m = idx >> 4, k = idx & 15;
            As[k][m] = A[(bm + m) * 256 + k0 + k];
        }
        {
            int k = tx >> 6, n = tx & 63;
            #pragma unroll
            for (int l = 0; l < 4; l++)
                Bs[k + l * 4][n] = B[(k0 + k + l * 4) * 256 + bn + n];
        }
        __syncthreads();
        #pragma unroll
        for (int k = 0; k < 16; k++) {
            float a[4], b[4];
            #pragma unroll
            for (int u = 0; u < 4; u++) a[u] = As[k][tm + u];
            #pragma unroll
            for (int v = 0; v < 4; v++) b[v] = Bs[k][tn + v];
            #pragma unroll
            for (int u = 0; u < 4; u++)
                #pragma unroll
                for (int v = 0; v < 4; v++) acc[u][v] += a[u] * b[v];
        }
        __syncthreads();
    }
    #pragma unroll
    for (int u = 0; u < 4; u++)
        #pragma unroll
        for (int v = 0; v < 4; v++)
            C[(bm + tm + u) * 256 + bn + tn + v] = acc[u][v];
}

// ---------------- kernel B: scores + factorized exponentials ----------------
__global__ __launch_bounds__(256) void scores_kernel(const float* __restrict__ a1,
                                                     const float* __restrict__ a2) {
    int warp = (blockIdx.x * blockDim.x + threadIdx.x) >> 5;
    int lane = threadIdx.x & 31;
    if (warp >= N_NODES * NH) return;
    int node = warp >> 2, head = warp & 3;
    const float* hp = g_h + node * HID + head * HD;
    float v0 = hp[lane], v1 = hp[lane + 32];
    float s1 = v0 * a1[lane] + v1 * a1[lane + 32];
    float s2 = v0 * a2[lane] + v1 * a2[lane + 32];
    #pragma unroll
    for (int o = 16; o > 0; o >>= 1) {
        s1 += __shfl_xor_sync(0xffffffffu, s1, o);
        s2 += __shfl_xor_sync(0xffffffffu, s2, o);
    }
    if (lane == 0) {
        int idx = head * N_NODES + node;
        g_s1[idx]  = s1;
        g_s2[idx]  = s2;
        g_e1i[idx] = __expf(s1);
        g_e2i[idx] = __expf(0.2f * s1);
        g_e1j[idx] = __expf(s2);
        g_e2j[idx] = __expf(0.2f * s2);
    }
}

// ---------------- kernel C: split-j flash-style tf32-MMA aggregation --------
// Block = (64 dest rows, head, j-slice). Writes unnormalized numerator slice
// + denominator slice to scratch; reduce_norm combines (deterministic order).
#define TM  64
#define TJ  64
#define PST 68   // P smem stride (A-frag LDS conflict-free)
#define VST 72   // V smem stride (B-frag LDS conflict-free)

__global__ __launch_bounds__(256) void attn_mma(const int* __restrict__ adj) {
    __shared__ float Psh[TM * PST];
    __shared__ float Vsh[TJ * VST];

    int t    = threadIdx.x;
    int lane = t & 31;
    int warp = t >> 5;
    int i0   = blockIdx.x * TM;
    int head = blockIdx.y;
    int sl   = blockIdx.z;
    int jbeg = sl * JSL;

    int m = t >> 2;
    int q = t & 3;

    float s1i = g_s1 [head * N_NODES + i0 + m];
    float e1i = g_e1i[head * N_NODES + i0 + m];
    float e2i = g_e2i[head * N_NODES + i0 + m];
    float dsum = 0.f;

    int mw = warp & 3;
    int nw = warp >> 2;
    float acc[4][4];
    #pragma unroll
    for (int a = 0; a < 4; a++)
        #pragma unroll
        for (int b = 0; b < 4; b++) acc[a][b] = 0.f;

    const int*   adjrow = adj + (size_t)(i0 + m) * N_NODES;
    const float* s2p = g_s2  + head * N_NODES;
    const float* e1p = g_e1j + head * N_NODES;
    const float* e2p = g_e2j + head * N_NODES;
    const float* vbase = g_h + head * HD;

    int vr = t >> 4;
    int vc = (t & 15) * 4;

    for (int j0 = jbeg; j0 < jbeg + JSL; j0 += TJ) {
        // ---- build P tile (tf32-quantized) + denominator partial ----
        #pragma unroll
        for (int u = 0; u < 4; u++) {
            int jc = q * 16 + u * 4;
            int j  = j0 + jc;
            int4   av  = *(const int4*)  (adjrow + j);
            float4 s2v = *(const float4*)(s2p + j);
            float4 e1v = *(const float4*)(e1p + j);
            float4 e2v = *(const float4*)(e2p + j);
            float w0 = (av.x > 0) ? ((s1i + s2v.x > 0.f) ? e1i * e1v.x : e2i * e2v.x) : 0.f;
            float w1 = (av.y > 0) ? ((s1i + s2v.y > 0.f) ? e1i * e1v.y : e2i * e2v.y) : 0.f;
            float w2 = (av.z > 0) ? ((s1i + s2v.z > 0.f) ? e1i * e1v.z : e2i * e2v.z) : 0.f;
            float w3 = (av.w > 0) ? ((s1i + s2v.w > 0.f) ? e1i * e1v.w : e2i * e2v.w) : 0.f;
            w0 = __uint_as_float(f2tf32(w0));
            w1 = __uint_as_float(f2tf32(w1));
            w2 = __uint_as_float(f2tf32(w2));
            w3 = __uint_as_float(f2tf32(w3));
            *(float4*)(Psh + m * PST + jc) = make_float4(w0, w1, w2, w3);
            dsum += (w0 + w1) + (w2 + w3);
        }

        // ---- load V tile [j'][d] for this head, rna-rounded to tf32 ----
        const float* vb = vbase + (size_t)j0 * HID;
        #pragma unroll
        for (int u = 0; u < 4; u++) {
            int jr = u * 16 + vr;
            float4 v = *(const float4*)(vb + (size_t)jr * HID + vc);
            *(float4*)(Vsh + jr * VST + vc) = make_float4(
                __uint_as_float(f2tf32(v.x)), __uint_as_float(f2tf32(v.y)),
                __uint_as_float(f2tf32(v.z)), __uint_as_float(f2tf32(v.w)));
        }
        __syncthreads();

        // ---- MMA: acc += P[mw*16 : +16][:] @ V[:][nw*32 : +32] ----
        const float* Pb = Psh + (mw * 16) * PST;
        const float* Vb = Vsh + nw * 32;
        int r = lane >> 2, c = lane & 3;
        #pragma unroll
        for (int k = 0; k < TJ; k += 8) {
            unsigned a0 = __float_as_uint(Pb[(r    ) * PST + k + c    ]);
            unsigned a1 = __float_as_uint(Pb[(r + 8) * PST + k + c    ]);
            unsigned a2 = __float_as_uint(Pb[(r    ) * PST + k + c + 4]);
            unsigned a3 = __float_as_uint(Pb[(r + 8) * PST + k + c + 4]);
            #pragma unroll
            for (int nt = 0; nt < 4; nt++) {
                unsigned b0 = __float_as_uint(Vb[(k + c    ) * VST + nt * 8 + r]);
                unsigned b1 = __float_as_uint(Vb[(k + c + 4) * VST + nt * 8 + r]);
                asm volatile(
                    "mma.sync.aligned.m16n8k8.row.col.f32.tf32.tf32.f32 "
                    "{%0,%1,%2,%3}, {%4,%5,%6,%7}, {%8,%9}, {%0,%1,%2,%3};\n"
                    : "+f"(acc[nt][0]), "+f"(acc[nt][1]),
                      "+f"(acc[nt][2]), "+f"(acc[nt][3])
                    : "r"(a0), "r"(a1), "r"(a2), "r"(a3), "r"(b0), "r"(b1));
            }
        }
        __syncthreads();
    }

    // ---- denominator slice: reduce over column-quarters q ----
    dsum += __shfl_xor_sync(0xffffffffu, dsum, 1);
    dsum += __shfl_xor_sync(0xffffffffu, dsum, 2);
    if (q == 0)
        g_den[(sl * NH + head) * N_NODES + i0 + m] = dsum;

    // ---- numerator slice write (unnormalized) ----
    float* nslice = g_num + (size_t)sl * (N_NODES * HID);
    int r = lane >> 2, c2 = (lane & 3) * 2;
    #pragma unroll
    for (int nt = 0; nt < 4; nt++) {
        int col  = head * HD + nw * 32 + nt * 8 + c2;
        int row0 = i0 + mw * 16 + r;
        *(float2*)(nslice + (size_t)row0 * HID + col) =
            make_float2(acc[nt][0], acc[nt][1]);
        *(float2*)(nslice + (size_t)(row0 + 8) * HID + col) =
            make_float2(acc[nt][2], acc[nt][3]);
    }
}

// ---------------- kernel D: combine slices + normalize ----------------------
__global__ __launch_bounds__(256) void reduce_norm(float* __restrict__ out) {
    int i = blockIdx.x;
    int c = threadIdx.x;
    size_t off = (size_t)i * HID + c;
    const size_t SL = (size_t)N_NODES * HID;
    float n = g_num[off] + g_num[SL + off] + g_num[2 * SL + off] + g_num[3 * SL + off];
    int head = c >> 6;
    int di = head * N_NODES + i;
    const int DN = NH * N_NODES;
    float d = g_den[di] + g_den[DN + di] + g_den[2 * DN + di] + g_den[3 * DN + di];
    out[off] = n / d;
}

// ---------------- launch ----------------
extern "C" void kernel_launch(void* const* d_in, const int* in_sizes, int n_in,
                              void* d_out, int out_size) {
    const float* x   = (const float*)d_in[0];   // [4096, 256]
    const int*   adj = (const int*)  d_in[1];   // [4096, 4096]
    const float* W   = (const float*)d_in[2];   // [256, 256]
    const float* a1  = (const float*)d_in[3];   // [64]
    const float* a2  = (const float*)d_in[4];   // [64]
    float* out = (float*)d_out;                 // [4096, 256]

    float* h_ptr;
    cudaGetSymbolAddress((void**)&h_ptr, g_h);

    dim3 ggrid(N_NODES / 64, HID / 64);
    gemm_hw<<<ggrid, 256>>>(x, W, h_ptr);

    scores_kernel<<<(N_NODES * NH * 32) / 256, 256>>>(a1, a2);

    attn_mma<<<dim3(N_NODES / TM, NH, NSLICE), 256>>>(adj);

    reduce_norm<<<N_NODES, 256>>>(out);
}

// round 9
// speedup vs baseline: 2.1258x; 1.3592x over previous
#include <cuda_runtime.h>
#include <cuda_fp16.h>
#include <math.h>

#define N_NODES 4096
#define IN_F    256
#define NH      4
#define HD      64
#define HID     256   // NH*HD
#define NSLICE  4
#define JSL     (N_NODES / NSLICE)   // 1024 j's per slice

// ---------------- scratch (device globals; no allocs allowed) ----------------
__device__ float    g_h  [N_NODES * HID];               // 4 MB fp32 h = x@W
__device__ __half   g_hT [NH * HD * N_NODES];           // 2 MB fp16 transposed: [head*64+d][j]
__device__ float    g_e1i[NH * N_NODES];
__device__ float    g_e2i[NH * N_NODES];
__device__ float    g_e1j[NH * N_NODES];
__device__ float    g_e2j[NH * N_NODES];
__device__ unsigned g_adjb[N_NODES * (N_NODES / 32)];   // 2 MB bit-packed adj
__device__ float    g_num[NSLICE * N_NODES * HID];      // 16 MB numerator slices
__device__ float    g_den[NSLICE * NH * N_NODES];

// ---------------- kernel A0: bit-pack adjacency ------------------------------
__global__ __launch_bounds__(256) void adjpack(const int* __restrict__ adj) {
    int warp = (blockIdx.x * blockDim.x + threadIdx.x) >> 5;   // = row i
    int lane = threadIdx.x & 31;
    const int* row = adj + (size_t)warp * N_NODES;
    unsigned* outw = g_adjb + warp * (N_NODES / 32);
    #pragma unroll 4
    for (int c = 0; c < N_NODES / 32; c++) {
        int v = row[c * 32 + lane];
        unsigned b = __ballot_sync(0xffffffffu, v > 0);
        if (lane == 0) outw[c] = b;
    }
}

// ---------------- kernel A: h = x @ W  + fp16-transposed epilogue ------------
__global__ __launch_bounds__(256) void gemm_hw(const float* __restrict__ A,
                                               const float* __restrict__ B,
                                               float* __restrict__ C) {
    __shared__ float As[16][65];
    __shared__ float Bs[16][65];
    __shared__ __half tileh[64 * 72];
    int tx = threadIdx.x;
    int bm = blockIdx.x * 64;
    int bn = blockIdx.y * 64;      // head = blockIdx.y (64-col tiles align with heads)
    int tm = (tx >> 4) * 4;
    int tn = (tx & 15) * 4;
    float acc[4][4] = {};
    for (int k0 = 0; k0 < 256; k0 += 16) {
        #pragma unroll
        for (int l = 0; l < 4; l++) {
            int idx = tx + l * 256;
            int m = idx >> 4, k = idx & 15;
            As[k][m] = A[(bm + m) * 256 + k0 + k];
        }
        {
            int k = tx >> 6, n = tx & 63;
            #pragma unroll
            for (int l = 0; l < 4; l++)
                Bs[k + l * 4][n] = B[(k0 + k + l * 4) * 256 + bn + n];
        }
        __syncthreads();
        #pragma unroll
        for (int k = 0; k < 16; k++) {
            float a[4], b[4];
            #pragma unroll
            for (int u = 0; u < 4; u++) a[u] = As[k][tm + u];
            #pragma unroll
            for (int v = 0; v < 4; v++) b[v] = Bs[k][tn + v];
            #pragma unroll
            for (int u = 0; u < 4; u++)
                #pragma unroll
                for (int v = 0; v < 4; v++) acc[u][v] += a[u] * b[v];
        }
        __syncthreads();
    }
    // fp32 output + stage fp16 transposed tile [d][j_local]
    #pragma unroll
    for (int u = 0; u < 4; u++)
        #pragma unroll
        for (int v = 0; v < 4; v++) {
            C[(size_t)(bm + tm + u) * 256 + bn + tn + v] = acc[u][v];
            tileh[(tn + v) * 72 + tm + u] = __float2half_rn(acc[u][v]);
        }
    __syncthreads();
    {
        int drow = tx >> 2, jseg = tx & 3;
        uint4 w0 = *(const uint4*)&tileh[drow * 72 + jseg * 16];
        uint4 w1 = *(const uint4*)&tileh[drow * 72 + jseg * 16 + 8];
        __half* dst = g_hT + (size_t)(bn + drow) * N_NODES + bm + jseg * 16;
        *(uint4*)dst = w0;
        *(uint4*)(dst + 8) = w1;
    }
}

// ---------------- kernel B: scores + factorized exponentials ----------------
__global__ __launch_bounds__(256) void scores_kernel(const float* __restrict__ a1,
                                                     const float* __restrict__ a2) {
    int warp = (blockIdx.x * blockDim.x + threadIdx.x) >> 5;
    int lane = threadIdx.x & 31;
    if (warp >= N_NODES * NH) return;
    int node = warp >> 2, head = warp & 3;
    const float* hp = g_h + node * HID + head * HD;
    float v0 = hp[lane], v1 = hp[lane + 32];
    float s1 = v0 * a1[lane] + v1 * a1[lane + 32];
    float s2 = v0 * a2[lane] + v1 * a2[lane + 32];
    #pragma unroll
    for (int o = 16; o > 0; o >>= 1) {
        s1 += __shfl_xor_sync(0xffffffffu, s1, o);
        s2 += __shfl_xor_sync(0xffffffffu, s2, o);
    }
    if (lane == 0) {
        int idx = head * N_NODES + node;
        g_e1i[idx] = __expf(s1);
        g_e2i[idx] = __expf(0.2f * s1);
        g_e1j[idx] = __expf(s2);
        g_e2j[idx] = __expf(0.2f * s2);
    }
}

// ---------------- kernel C: split-j fp16-MMA masked-softmax aggregation -----
// w(i,j) = adj ? max(e^si·e^sj, e^{.2si}·e^{.2sj}) : 0   (= exp(lrelu(si+sj)))
#define TM   64
#define TJ   64
#define PSTH 72   // halves (144 B rows: ldmatrix conflict-free)

__global__ __launch_bounds__(256) void attn_mma() {
    __shared__ __align__(16) __half Ph[TM * PSTH];
    __shared__ __align__(16) __half Vt[HD * PSTH];

    int t    = threadIdx.x;
    int lane = t & 31;
    int warp = t >> 5;
    int i0   = blockIdx.x * TM;
    int head = blockIdx.y;
    int sl   = blockIdx.z;
    int jbeg = sl * JSL;

    int m = t >> 2;          // P-build row / V-copy d-row
    int q = t & 3;           // P-build 16-j quarter / V-copy 16-j segment

    float e1i = g_e1i[head * N_NODES + i0 + m];
    float e2i = g_e2i[head * N_NODES + i0 + m];
    float dsum = 0.f;

    int mw = warp & 3;
    int nw = warp >> 2;
    float acc[4][4];
    #pragma unroll
    for (int a = 0; a < 4; a++)
        #pragma unroll
        for (int b = 0; b < 4; b++) acc[a][b] = 0.f;

    const unsigned* adjw = g_adjb + (size_t)(i0 + m) * (N_NODES / 32);
    const float*  e1p  = g_e1j + head * N_NODES;
    const float*  e2p  = g_e2j + head * N_NODES;
    const __half* vsrc = g_hT + (size_t)(head * HD + m) * N_NODES + q * 16;

    unsigned pA, vB;
    {
        unsigned phb = (unsigned)__cvta_generic_to_shared(Ph);
        unsigned vtb = (unsigned)__cvta_generic_to_shared(Vt);
        pA = phb + (mw * 16 + (lane & 15)) * (PSTH * 2) + (lane >> 4) * 16;
        vB = vtb + (nw * 32 + (lane & 7)) * (PSTH * 2) + ((lane >> 3) & 1) * 16;
    }

    for (int j0 = jbeg; j0 < jbeg + JSL; j0 += TJ) {
        // ---- V tile copy (fp16, pre-transposed, pre-rounded) ----
        const __half* vs = vsrc + j0;
        uint4 va = *(const uint4*)(vs);
        uint4 vb = *(const uint4*)(vs + 8);

        // ---- P tile build ----
        unsigned word = adjw[(j0 >> 5) + (q >> 1)];
        unsigned bits = word >> ((q & 1) * 16);
        #pragma unroll
        for (int u = 0; u < 4; u++) {
            int jc = q * 16 + u * 4;
            int j  = j0 + jc;
            float4 e1v = *(const float4*)(e1p + j);
            float4 e2v = *(const float4*)(e2p + j);
            float w0 = (bits & (1u << (u * 4 + 0))) ? fmaxf(e1i * e1v.x, e2i * e2v.x) : 0.f;
            float w1 = (bits & (1u << (u * 4 + 1))) ? fmaxf(e1i * e1v.y, e2i * e2v.y) : 0.f;
            float w2 = (bits & (1u << (u * 4 + 2))) ? fmaxf(e1i * e1v.z, e2i * e2v.z) : 0.f;
            float w3 = (bits & (1u << (u * 4 + 3))) ? fmaxf(e1i * e1v.w, e2i * e2v.w) : 0.f;
            dsum += (w0 + w1) + (w2 + w3);
            __half2* pd = (__half2*)&Ph[m * PSTH + jc];
            pd[0] = __floats2half2_rn(w0, w1);
            pd[1] = __floats2half2_rn(w2, w3);
        }
        {
            __half* vd = &Vt[m * PSTH + q * 16];
            *(uint4*)vd = va;
            *(uint4*)(vd + 8) = vb;
        }
        __syncthreads();

        // ---- MMA: acc += P[mw*16:+16][0:64] @ Vt[0:64][nw*32:+32]^T ----
        #pragma unroll
        for (int ks = 0; ks < 4; ks++) {
            unsigned a0, a1, a2, a3;
            asm volatile("ldmatrix.sync.aligned.m8n8.x4.shared.b16 {%0,%1,%2,%3}, [%4];"
                         : "=r"(a0), "=r"(a1), "=r"(a2), "=r"(a3)
                         : "r"(pA + ks * 32));
            #pragma unroll
            for (int nt = 0; nt < 4; nt++) {
                unsigned b0, b1;
                asm volatile("ldmatrix.sync.aligned.m8n8.x2.shared.b16 {%0,%1}, [%2];"
                             : "=r"(b0), "=r"(b1)
                             : "r"(vB + nt * 8 * (PSTH * 2) + ks * 32));
                asm volatile(
                    "mma.sync.aligned.m16n8k16.row.col.f32.f16.f16.f32 "
                    "{%0,%1,%2,%3}, {%4,%5,%6,%7}, {%8,%9}, {%0,%1,%2,%3};\n"
                    : "+f"(acc[nt][0]), "+f"(acc[nt][1]),
                      "+f"(acc[nt][2]), "+f"(acc[nt][3])
                    : "r"(a0), "r"(a1), "r"(a2), "r"(a3), "r"(b0), "r"(b1));
            }
        }
        __syncthreads();
    }

    // ---- denominator slice: reduce over quarters q (lane bits 0-1) ----
    dsum += __shfl_xor_sync(0xffffffffu, dsum, 1);
    dsum += __shfl_xor_sync(0xffffffffu, dsum, 2);
    if (q == 0)
        g_den[(sl * NH + head) * N_NODES + i0 + m] = dsum;

    // ---- numerator slice write ----
    float* nslice = g_num + (size_t)sl * (N_NODES * HID);
    int r = lane >> 2, c2 = (lane & 3) * 2;
    #pragma unroll
    for (int nt = 0; nt < 4; nt++) {
        int col  = head * HD + nw * 32 + nt * 8 + c2;
        int row0 = i0 + mw * 16 + r;
        *(float2*)(nslice + (size_t)row0 * HID + col) =
            make_float2(acc[nt][0], acc[nt][1]);
        *(float2*)(nslice + (size_t)(row0 + 8) * HID + col) =
            make_float2(acc[nt][2], acc[nt][3]);
    }
}

// ---------------- kernel D: combine slices + normalize (float4) -------------
__global__ __launch_bounds__(256) void reduce_norm(float* __restrict__ out) {
    int f = blockIdx.x * 256 + threadIdx.x;      // float4 index
    int i    = f >> 6;                           // 64 float4 per row
    int c4   = f & 63;
    int head = c4 >> 4;
    const float4* n4 = (const float4*)g_num;
    const size_t SL4 = (size_t)N_NODES * HID / 4;
    float4 A = n4[f], B = n4[SL4 + f], C = n4[2 * SL4 + f], D = n4[3 * SL4 + f];
    int di = head * N_NODES + i;
    const int DN = NH * N_NODES;
    float d = g_den[di] + g_den[DN + di] + g_den[2 * DN + di] + g_den[3 * DN + di];
    float inv = 1.f / d;
    float4 R;
    R.x = (A.x + B.x + C.x + D.x) * inv;
    R.y = (A.y + B.y + C.y + D.y) * inv;
    R.z = (A.z + B.z + C.z + D.z) * inv;
    R.w = (A.w + B.w + C.w + D.w) * inv;
    ((float4*)out)[f] = R;
}

// ---------------- launch ----------------
extern "C" void kernel_launch(void* const* d_in, const int* in_sizes, int n_in,
                              void* d_out, int out_size) {
    const float* x   = (const float*)d_in[0];   // [4096, 256]
    const int*   adj = (const int*)  d_in[1];   // [4096, 4096]
    const float* W   = (const float*)d_in[2];   // [256, 256]
    const float* a1  = (const float*)d_in[3];   // [64]
    const float* a2  = (const float*)d_in[4];   // [64]
    float* out = (float*)d_out;                 // [4096, 256]

    float* h_ptr;
    cudaGetSymbolAddress((void**)&h_ptr, g_h);

    adjpack<<<N_NODES / 8, 256>>>(adj);

    dim3 ggrid(N_NODES / 64, HID / 64);
    gemm_hw<<<ggrid, 256>>>(x, W, h_ptr);

    scores_kernel<<<(N_NODES * NH * 32) / 256, 256>>>(a1, a2);

    attn_mma<<<dim3(N_NODES / TM, NH, NSLICE), 256>>>();

    reduce_norm<<<(N_NODES * HID / 4) / 256, 256>>>(out);
}

// round 13
// speedup vs baseline: 2.2984x; 1.0812x over previous
#include <cuda_runtime.h>
#include <cuda_fp16.h>
#include <math.h>

#define N_NODES 4096
#define IN_F    256
#define NH      4
#define HD      64
#define HID     256   // NH*HD
#define NSLICE  4
#define JSL     (N_NODES / NSLICE)   // 1024 j's per slice
#define TM      64
#define TJ      64

// ---------------- scratch (device globals; no allocs allowed) ----------------
__device__ float    g_h  [N_NODES * HID];               // 4 MB fp32 h = x@W
__device__ __half   g_hT [NH * HD * N_NODES];           // 2 MB fp16 [head*64+d][j]
__device__ float2   g_eip[NH * N_NODES];                // (e^s1, e^{.2 s1})
__device__ float2   g_ejp[NH * N_NODES];                // (e^s2, e^{.2 s2})
__device__ unsigned g_adjb[N_NODES * (N_NODES / 32)];   // 2 MB bit-packed adj
__device__ float    g_num[NSLICE * N_NODES * HID];      // 16 MB numerator slices
__device__ float    g_den[NSLICE * NH * N_NODES];

__device__ __forceinline__ unsigned h2_as_u32(__half2 h) {
    __half2_raw r = *(__half2_raw*)&h;
    return ((unsigned)r.y << 16) | (unsigned)r.x;
}

// ---------------- kernel A0: bit-pack adjacency ------------------------------
__global__ __launch_bounds__(256) void adjpack(const int* __restrict__ adj) {
    int warp = (blockIdx.x * blockDim.x + threadIdx.x) >> 5;   // = row i
    int lane = threadIdx.x & 31;
    const int* row = adj + (size_t)warp * N_NODES;
    unsigned* outw = g_adjb + warp * (N_NODES / 32);
    #pragma unroll 4
    for (int c = 0; c < N_NODES / 32; c++) {
        int v = row[c * 32 + lane];
        unsigned b = __ballot_sync(0xffffffffu, v > 0);
        if (lane == 0) outw[c] = b;
    }
}

// ---------------- kernel A: h = x @ W (32x64 tiles) + fp16-T epilogue --------
__global__ __launch_bounds__(256) void gemm_hw(const float* __restrict__ A,
                                               const float* __restrict__ B,
                                               float* __restrict__ C) {
    __shared__ float As[16][33];
    __shared__ float Bs[16][65];
    __shared__ __half tileh[64 * 40];     // [d][j_local], stride 40
    int tx = threadIdx.x;
    int bm = blockIdx.x * 32;
    int bn = blockIdx.y * 64;             // head = blockIdx.y
    int tm = (tx >> 4) * 2;
    int tn = (tx & 15) * 4;
    float acc[2][4] = {};
    for (int k0 = 0; k0 < 256; k0 += 16) {
        #pragma unroll
        for (int l = 0; l < 2; l++) {
            int idx = tx + l * 256;
            int m = idx >> 4, k = idx & 15;
            As[k][m] = A[(bm + m) * 256 + k0 + k];
        }
        {
            int k = tx >> 6, n = tx & 63;
            #pragma unroll
            for (int l = 0; l < 4; l++)
                Bs[k + l * 4][n] = B[(k0 + k + l * 4) * 256 + bn + n];
        }
        __syncthreads();
        #pragma unroll
        for (int k = 0; k < 16; k++) {
            float a[2], b[4];
            a[0] = As[k][tm]; a[1] = As[k][tm + 1];
            #pragma unroll
            for (int v = 0; v < 4; v++) b[v] = Bs[k][tn + v];
            #pragma unroll
            for (int u = 0; u < 2; u++)
                #pragma unroll
                for (int v = 0; v < 4; v++) acc[u][v] += a[u] * b[v];
        }
        __syncthreads();
    }
    #pragma unroll
    for (int u = 0; u < 2; u++)
        #pragma unroll
        for (int v = 0; v < 4; v++) {
            C[(size_t)(bm + tm + u) * 256 + bn + tn + v] = acc[u][v];
            tileh[(tn + v) * 40 + tm + u] = __float2half_rn(acc[u][v]);
        }
    __syncthreads();
    {
        int drow = tx >> 2, seg = tx & 3;       // 64 d-rows x 4 segs x 8 halves
        uint4 w = *(const uint4*)&tileh[drow * 40 + seg * 8];
        *(uint4*)(g_hT + (size_t)(bn + drow) * N_NODES + bm + seg * 8) = w;
    }
}

// ---------------- kernel B: scores + factorized exponential pairs -----------
__global__ __launch_bounds__(256) void scores_kernel(const float* __restrict__ a1,
                                                     const float* __restrict__ a2) {
    int warp = (blockIdx.x * blockDim.x + threadIdx.x) >> 5;
    int lane = threadIdx.x & 31;
    if (warp >= N_NODES * NH) return;
    int node = warp >> 2, head = warp & 3;
    const float* hp = g_h + node * HID + head * HD;
    float v0 = hp[lane], v1 = hp[lane + 32];
    float s1 = v0 * a1[lane] + v1 * a1[lane + 32];
    float s2 = v0 * a2[lane] + v1 * a2[lane + 32];
    #pragma unroll
    for (int o = 16; o > 0; o >>= 1) {
        s1 += __shfl_xor_sync(0xffffffffu, s1, o);
        s2 += __shfl_xor_sync(0xffffffffu, s2, o);
    }
    if (lane == 0) {
        int idx = head * N_NODES + node;
        g_eip[idx] = make_float2(__expf(s1), __expf(0.2f * s1));
        g_ejp[idx] = make_float2(__expf(s2), __expf(0.2f * s2));
    }
}

// ---------------- kernel C: split-j fp16-MMA, A-fragments built in regs -----
// w(i,j) = adj ? max(e^si·e^sj, e^{.2si}·e^{.2sj}) : 0
__global__ __launch_bounds__(256) void attn_mma() {
    __shared__ float2   esh[JSL];                    // 8 KB (e1j,e2j) pairs
    __shared__ unsigned adjSh[TM * (JSL / 32)];      // 8 KB block's adj slice
    __shared__ __align__(16) __half Vt[2][HD * 72];  // 18 KB double-buffered V

    int t    = threadIdx.x;
    int lane = t & 31;
    int warp = t >> 5;
    int i0   = blockIdx.x * TM;
    int head = blockIdx.y;
    int sl   = blockIdx.z;
    int jbeg = sl * JSL;

    int mw = warp & 3, nw = warp >> 2;
    int gid = lane >> 2, c2 = (lane & 3) * 2;
    int r = mw * 16 + gid;

    // ---- stage e-pairs + adj slice into smem (once per block) ----
    #pragma unroll
    for (int k = 0; k < 4; k++)
        esh[t + k * 256] = g_ejp[head * N_NODES + jbeg + t + k * 256];
    {
        int rr = t >> 2, seg = t & 3;
        const uint4* src = (const uint4*)(g_adjb + (size_t)(i0 + rr) * (N_NODES / 32) + (jbeg >> 5));
        uint4* dst = (uint4*)&adjSh[rr * 32];
        dst[seg * 2]     = src[seg * 2];
        dst[seg * 2 + 1] = src[seg * 2 + 1];
    }

    float2 eiA = g_eip[head * N_NODES + i0 + r];
    float2 eiB = g_eip[head * N_NODES + i0 + r + 8];
    float dsA = 0.f, dsB = 0.f;
    float acc[4][4];
    #pragma unroll
    for (int a = 0; a < 4; a++)
        #pragma unroll
        for (int b = 0; b < 4; b++) acc[a][b] = 0.f;

    int m = t >> 2, q = t & 3;   // V-copy identity
    const __half* vsrc = g_hT + (size_t)(head * HD + m) * N_NODES + jbeg + q * 16;

    unsigned vB0;
    {
        unsigned vtb = (unsigned)__cvta_generic_to_shared(&Vt[0][0]);
        vB0 = vtb + (nw * 32 + (lane & 7) + ((lane >> 3) & 1) * 8) * 144 + (lane >> 4) * 16;
    }

    __syncthreads();   // staging visible

    for (int c = 0; c < JSL / TJ; c++) {
        int buf = c & 1;
        // ---- V tile copy into buf ----
        const __half* vs = vsrc + c * TJ;
        uint4 va = *(const uint4*)vs;
        uint4 vb = *(const uint4*)(vs + 8);
        __half* vd = &Vt[buf][m * 72 + q * 16];
        *(uint4*)vd = va;
        *(uint4*)(vd + 8) = vb;

        // ---- adj words for rows r, r+8 (this 64-j chunk) ----
        uint2 wA = *(const uint2*)&adjSh[r * 32 + c * 2];
        uint2 wB = *(const uint2*)&adjSh[(r + 8) * 32 + c * 2];

        __syncthreads();   // V(buf) ready; prev buf reads done

        unsigned vBb = vB0 + buf * (HD * 72 * 2);
        const float4* e4 = (const float4*)esh;

        #pragma unroll
        for (int ks = 0; ks < 4; ks++) {
            // ---- build A fragment in registers ----
            float4 eLo = e4[(c * TJ + ks * 16 + c2) >> 1];
            float4 eHi = e4[(c * TJ + ks * 16 + c2 + 8) >> 1];
            unsigned wordA = (ks < 2) ? wA.x : wA.y;
            unsigned wordB = (ks < 2) ? wB.x : wB.y;
            int b = (ks & 1) * 16 + c2;
            float w00 = ((wordA >> b) & 1)       ? fmaxf(eiA.x * eLo.x, eiA.y * eLo.y) : 0.f;
            float w01 = ((wordA >> (b + 1)) & 1) ? fmaxf(eiA.x * eLo.z, eiA.y * eLo.w) : 0.f;
            float w02 = ((wordA >> (b + 8)) & 1) ? fmaxf(eiA.x * eHi.x, eiA.y * eHi.y) : 0.f;
            float w03 = ((wordA >> (b + 9)) & 1) ? fmaxf(eiA.x * eHi.z, eiA.y * eHi.w) : 0.f;
            float w10 = ((wordB >> b) & 1)       ? fmaxf(eiB.x * eLo.x, eiB.y * eLo.y) : 0.f;
            float w11 = ((wordB >> (b + 1)) & 1) ? fmaxf(eiB.x * eLo.z, eiB.y * eLo.w) : 0.f;
            float w12 = ((wordB >> (b + 8)) & 1) ? fmaxf(eiB.x * eHi.x, eiB.y * eHi.y) : 0.f;
            float w13 = ((wordB >> (b + 9)) & 1) ? fmaxf(eiB.x * eHi.z, eiB.y * eHi.w) : 0.f;
            if (nw == 0) {
                dsA += (w00 + w01) + (w02 + w03);
                dsB += (w10 + w11) + (w12 + w13);
            }
            unsigned a0 = h2_as_u32(__floats2half2_rn(w00, w01));
            unsigned a1 = h2_as_u32(__floats2half2_rn(w10, w11));
            unsigned a2 = h2_as_u32(__floats2half2_rn(w02, w03));
            unsigned a3 = h2_as_u32(__floats2half2_rn(w12, w13));

            // ---- B fragments (x4 = two nt) + MMA ----
            #pragma unroll
            for (int nt2 = 0; nt2 < 2; nt2++) {
                unsigned b0, b1, b2, b3;
                asm volatile("ldmatrix.sync.aligned.m8n8.x4.shared.b16 {%0,%1,%2,%3}, [%4];"
                             : "=r"(b0), "=r"(b1), "=r"(b2), "=r"(b3)
                             : "r"(vBb + nt2 * 16 * 144 + ks * 32));
                asm volatile(
                    "mma.sync.aligned.m16n8k16.row.col.f32.f16.f16.f32 "
                    "{%0,%1,%2,%3}, {%4,%5,%6,%7}, {%8,%9}, {%0,%1,%2,%3};\n"
                    : "+f"(acc[nt2 * 2][0]), "+f"(acc[nt2 * 2][1]),
                      "+f"(acc[nt2 * 2][2]), "+f"(acc[nt2 * 2][3])
                    : "r"(a0), "r"(a1), "r"(a2), "r"(a3), "r"(b0), "r"(b2));
                asm volatile(
                    "mma.sync.aligned.m16n8k16.row.col.f32.f16.f16.f32 "
                    "{%0,%1,%2,%3}, {%4,%5,%6,%7}, {%8,%9}, {%0,%1,%2,%3};\n"
                    : "+f"(acc[nt2 * 2 + 1][0]), "+f"(acc[nt2 * 2 + 1][1]),
                      "+f"(acc[nt2 * 2 + 1][2]), "+f"(acc[nt2 * 2 + 1][3])
                    : "r"(a0), "r"(a1), "r"(a2), "r"(a3), "r"(b1), "r"(b3));
            }
        }
    }

    // ---- denominator: reduce over the 4 lanes sharing a row ----
    dsA += __shfl_xor_sync(0xffffffffu, dsA, 1);
    dsA += __shfl_xor_sync(0xffffffffu, dsA, 2);
    dsB += __shfl_xor_sync(0xffffffffu, dsB, 1);
    dsB += __shfl_xor_sync(0xffffffffu, dsB, 2);
    if (nw == 0 && (lane & 3) == 0) {
        g_den[(sl * NH + head) * N_NODES + i0 + r]     = dsA;
        g_den[(sl * NH + head) * N_NODES + i0 + r + 8] = dsB;
    }

    // ---- numerator slice write ----
    float* nslice = g_num + (size_t)sl * (N_NODES * HID);
    int rr = lane >> 2, cc2 = (lane & 3) * 2;
    #pragma unroll
    for (int nt = 0; nt < 4; nt++) {
        int col  = head * HD + nw * 32 + nt * 8 + cc2;
        int row0 = i0 + mw * 16 + rr;
        *(float2*)(nslice + (size_t)row0 * HID + col) =
            make_float2(acc[nt][0], acc[nt][1]);
        *(float2*)(nslice + (size_t)(row0 + 8) * HID + col) =
            make_float2(acc[nt][2], acc[nt][3]);
    }
}

// ---------------- kernel D: combine slices + normalize (float4) -------------
__global__ __launch_bounds__(256) void reduce_norm(float* __restrict__ out) {
    int f = blockIdx.x * 256 + threadIdx.x;      // float4 index
    int i    = f >> 6;
    int c4   = f & 63;
    int head = c4 >> 4;
    const float4* n4 = (const float4*)g_num;
    const size_t SL4 = (size_t)N_NODES * HID / 4;
    float4 A = n4[f], B = n4[SL4 + f], C = n4[2 * SL4 + f], D = n4[3 * SL4 + f];
    int di = head * N_NODES + i;
    const int DN = NH * N_NODES;
    float d = g_den[di] + g_den[DN + di] + g_den[2 * DN + di] + g_den[3 * DN + di];
    float inv = 1.f / d;
    float4 R;
    R.x = (A.x + B.x + C.x + D.x) * inv;
    R.y = (A.y + B.y + C.y + D.y) * inv;
    R.z = (A.z + B.z + C.z + D.z) * inv;
    R.w = (A.w + B.w + C.w + D.w) * inv;
    ((float4*)out)[f] = R;
}

// ---------------- launch ----------------
extern "C" void kernel_launch(void* const* d_in, const int* in_sizes, int n_in,
                              void* d_out, int out_size) {
    const float* x   = (const float*)d_in[0];   // [4096, 256]
    const int*   adj = (const int*)  d_in[1];   // [4096, 4096]
    const float* W   = (const float*)d_in[2];   // [256, 256]
    const float* a1  = (const float*)d_in[3];   // [64]
    const float* a2  = (const float*)d_in[4];   // [64]
    float* out = (float*)d_out;                 // [4096, 256]

    float* h_ptr;
    cudaGetSymbolAddress((void**)&h_ptr, g_h);

    adjpack<<<N_NODES / 8, 256>>>(adj);

    dim3 ggrid(N_NODES / 32, HID / 64);
    gemm_hw<<<ggrid, 256>>>(x, W, h_ptr);

    scores_kernel<<<(N_NODES * NH * 32) / 256, 256>>>(a1, a2);

    attn_mma<<<dim3(N_NODES / TM, NH, NSLICE), 256>>>();

    reduce_norm<<<(N_NODES * HID / 4) / 256, 256>>>(out);
}

// round 15
// speedup vs baseline: 2.5015x; 1.0884x over previous
#include <cuda_runtime.h>
#include <cuda_fp16.h>
#include <math.h>

#define N_NODES 4096
#define IN_F    256
#define NH      4
#define HD      64
#define HID     256   // NH*HD
#define NSLICE  4
#define JSL     (N_NODES / NSLICE)   // 1024 j's per slice
#define TM      128
#define TJ      64

// ---------------- scratch (device globals; no allocs allowed) ----------------
__device__ float    g_h  [N_NODES * HID];               // 4 MB fp32 h = x@W
__device__ __half   g_hT [NH * HD * N_NODES];           // 2 MB fp16 [head*64+d][j]
__device__ float2   g_eip[NH * N_NODES];                // (e^s1, e^{.2 s1})
__device__ float2   g_ejp[NH * N_NODES];                // (e^s2, e^{.2 s2})
__device__ unsigned g_adjb[N_NODES * (N_NODES / 32)];   // 2 MB bit-packed adj
__device__ float    g_num[NSLICE * N_NODES * HID];      // 16 MB numerator slices
__device__ float    g_den[NSLICE * NH * N_NODES];

__device__ __forceinline__ unsigned h2_as_u32(__half2 h) {
    __half2_raw r = *(__half2_raw*)&h;
    return ((unsigned)r.y << 16) | (unsigned)r.x;
}

// ---------------- kernel A0: bit-pack adjacency ------------------------------
__global__ __launch_bounds__(256) void adjpack(const int* __restrict__ adj) {
    int warp = (blockIdx.x * blockDim.x + threadIdx.x) >> 5;   // = row i
    int lane = threadIdx.x & 31;
    const int* row = adj + (size_t)warp * N_NODES;
    unsigned* outw = g_adjb + warp * (N_NODES / 32);
    #pragma unroll 4
    for (int c = 0; c < N_NODES / 32; c++) {
        int v = row[c * 32 + lane];
        unsigned b = __ballot_sync(0xffffffffu, v > 0);
        if (lane == 0) outw[c] = b;
    }
}

// ---------------- kernel A: h = x @ W (32x64 tiles) + fp16-T epilogue --------
__global__ __launch_bounds__(256) void gemm_hw(const float* __restrict__ A,
                                               const float* __restrict__ B,
                                               float* __restrict__ C) {
    __shared__ float As[16][33];
    __shared__ float Bs[16][65];
    __shared__ __half tileh[64 * 40];     // [d][j_local], stride 40
    int tx = threadIdx.x;
    int bm = blockIdx.x * 32;
    int bn = blockIdx.y * 64;             // head = blockIdx.y
    int tm = (tx >> 4) * 2;
    int tn = (tx & 15) * 4;
    float acc[2][4] = {};
    for (int k0 = 0; k0 < 256; k0 += 16) {
        #pragma unroll
        for (int l = 0; l < 2; l++) {
            int idx = tx + l * 256;
            int m = idx >> 4, k = idx & 15;
            As[k][m] = A[(bm + m) * 256 + k0 + k];
        }
        {
            int k = tx >> 6, n = tx & 63;
            #pragma unroll
            for (int l = 0; l < 4; l++)
                Bs[k + l * 4][n] = B[(k0 + k + l * 4) * 256 + bn + n];
        }
        __syncthreads();
        #pragma unroll
        for (int k = 0; k < 16; k++) {
            float a[2], b[4];
            a[0] = As[k][tm]; a[1] = As[k][tm + 1];
            #pragma unroll
            for (int v = 0; v < 4; v++) b[v] = Bs[k][tn + v];
            #pragma unroll
            for (int u = 0; u < 2; u++)
                #pragma unroll
                for (int v = 0; v < 4; v++) acc[u][v] += a[u] * b[v];
        }
        __syncthreads();
    }
    #pragma unroll
    for (int u = 0; u < 2; u++)
        #pragma unroll
        for (int v = 0; v < 4; v++) {
            C[(size_t)(bm + tm + u) * 256 + bn + tn + v] = acc[u][v];
            tileh[(tn + v) * 40 + tm + u] = __float2half_rn(acc[u][v]);
        }
    __syncthreads();
    {
        int drow = tx >> 2, seg = tx & 3;       // 64 d-rows x 4 segs x 8 halves
        uint4 w = *(const uint4*)&tileh[drow * 40 + seg * 8];
        *(uint4*)(g_hT + (size_t)(bn + drow) * N_NODES + bm + seg * 8) = w;
    }
}

// ---------------- kernel B: scores + factorized exponential pairs -----------
__global__ __launch_bounds__(256) void scores_kernel(const float* __restrict__ a1,
                                                     const float* __restrict__ a2) {
    int warp = (blockIdx.x * blockDim.x + threadIdx.x) >> 5;
    int lane = threadIdx.x & 31;
    if (warp >= N_NODES * NH) return;
    int node = warp >> 2, head = warp & 3;
    const float* hp = g_h + node * HID + head * HD;
    float v0 = hp[lane], v1 = hp[lane + 32];
    float s1 = v0 * a1[lane] + v1 * a1[lane + 32];
    float s2 = v0 * a2[lane] + v1 * a2[lane + 32];
    #pragma unroll
    for (int o = 16; o > 0; o >>= 1) {
        s1 += __shfl_xor_sync(0xffffffffu, s1, o);
        s2 += __shfl_xor_sync(0xffffffffu, s2, o);
    }
    if (lane == 0) {
        int idx = head * N_NODES + node;
        g_eip[idx] = make_float2(__expf(s1), __expf(0.2f * s1));
        g_ejp[idx] = make_float2(__expf(s2), __expf(0.2f * s2));
    }
}

// ---------------- kernel C: split-j fp16-MMA, TM=128, 1 warp = 16 rows ------
// w(i,j) = adj ? max(e^si·e^sj, e^{.2si}·e^{.2sj}) : 0; denominator = P @ 1.
__global__ __launch_bounds__(256) void attn_mma() {
    __shared__ float2   esh[JSL];                    // 8 KB (e1j,e2j) pairs
    __shared__ unsigned adjSh[TM * (JSL / 32)];      // 16 KB block's adj slice
    __shared__ __align__(16) __half Vt[2][HD * 72];  // 18 KB double-buffered V

    int t    = threadIdx.x;
    int lane = t & 31;
    int warp = t >> 5;                   // 0..7: owns rows warp*16..+15
    int i0   = blockIdx.x * TM;
    int head = blockIdx.y;
    int sl   = blockIdx.z;
    int jbeg = sl * JSL;

    int gid = lane >> 2, c2 = (lane & 3) * 2;
    int r = warp * 16 + gid;

    // ---- stage e-pairs + adj slice into smem (once per block) ----
    #pragma unroll
    for (int k = 0; k < 4; k++)
        esh[t + k * 256] = g_ejp[head * N_NODES + jbeg + t + k * 256];
    {
        int rr = t >> 1, seg = t & 1;    // 128 rows x 32 words; 16 words/thread
        const uint4* src = (const uint4*)(g_adjb + (size_t)(i0 + rr) * (N_NODES / 32) + (jbeg >> 5));
        uint4* dst = (uint4*)&adjSh[rr * 32];
        #pragma unroll
        for (int u = 0; u < 4; u++)
            dst[seg * 4 + u] = src[seg * 4 + u];
    }

    float2 eiA = g_eip[head * N_NODES + i0 + r];
    float2 eiB = g_eip[head * N_NODES + i0 + r + 8];
    float acc[8][4];
    #pragma unroll
    for (int a = 0; a < 8; a++)
        #pragma unroll
        for (int b = 0; b < 4; b++) acc[a][b] = 0.f;
    float accd[4] = {0.f, 0.f, 0.f, 0.f};
    const unsigned ONES2 = 0x3C003C00u;  // half2(1,1)

    int m = t >> 2, q = t & 3;           // V-copy identity (64 d-rows x 4 segs)
    const __half* vsrc = g_hT + (size_t)(head * HD + m) * N_NODES + jbeg + q * 16;

    unsigned vB0;
    {
        unsigned vtb = (unsigned)__cvta_generic_to_shared(&Vt[0][0]);
        vB0 = vtb + ((lane & 7) + ((lane >> 3) & 1) * 8) * 144 + (lane >> 4) * 16;
    }

    __syncthreads();   // staging visible

    for (int c = 0; c < JSL / TJ; c++) {
        int buf = c & 1;
        // ---- V tile copy into buf ----
        const __half* vs = vsrc + c * TJ;
        uint4 va = *(const uint4*)vs;
        uint4 vb = *(const uint4*)(vs + 8);
        __half* vd = &Vt[buf][m * 72 + q * 16];
        *(uint4*)vd = va;
        *(uint4*)(vd + 8) = vb;

        // ---- adj words for rows r, r+8 (this 64-j chunk) ----
        uint2 wA = *(const uint2*)&adjSh[r * 32 + c * 2];
        uint2 wB = *(const uint2*)&adjSh[(r + 8) * 32 + c * 2];

        __syncthreads();   // V(buf) ready; prev buf reads done

        unsigned vBb = vB0 + buf * (HD * 72 * 2);
        const float4* e4 = (const float4*)esh;

        #pragma unroll
        for (int ks = 0; ks < 4; ks++) {
            // ---- build A fragment in registers ----
            float4 eLo = e4[(c * TJ + ks * 16 + c2) >> 1];
            float4 eHi = e4[(c * TJ + ks * 16 + c2 + 8) >> 1];
            unsigned wordA = (ks < 2) ? wA.x : wA.y;
            unsigned wordB = (ks < 2) ? wB.x : wB.y;
            int b = (ks & 1) * 16 + c2;
            float w00 = ((wordA >> b) & 1)       ? fmaxf(eiA.x * eLo.x, eiA.y * eLo.y) : 0.f;
            float w01 = ((wordA >> (b + 1)) & 1) ? fmaxf(eiA.x * eLo.z, eiA.y * eLo.w) : 0.f;
            float w02 = ((wordA >> (b + 8)) & 1) ? fmaxf(eiA.x * eHi.x, eiA.y * eHi.y) : 0.f;
            float w03 = ((wordA >> (b + 9)) & 1) ? fmaxf(eiA.x * eHi.z, eiA.y * eHi.w) : 0.f;
            float w10 = ((wordB >> b) & 1)       ? fmaxf(eiB.x * eLo.x, eiB.y * eLo.y) : 0.f;
            float w11 = ((wordB >> (b + 1)) & 1) ? fmaxf(eiB.x * eLo.z, eiB.y * eLo.w) : 0.f;
            float w12 = ((wordB >> (b + 8)) & 1) ? fmaxf(eiB.x * eHi.x, eiB.y * eHi.y) : 0.f;
            float w13 = ((wordB >> (b + 9)) & 1) ? fmaxf(eiB.x * eHi.z, eiB.y * eHi.w) : 0.f;
            unsigned a0 = h2_as_u32(__floats2half2_rn(w00, w01));
            unsigned a1 = h2_as_u32(__floats2half2_rn(w10, w11));
            unsigned a2 = h2_as_u32(__floats2half2_rn(w02, w03));
            unsigned a3 = h2_as_u32(__floats2half2_rn(w12, w13));

            // ---- denominator: P @ ones via one MMA ----
            asm volatile(
                "mma.sync.aligned.m16n8k16.row.col.f32.f16.f16.f32 "
                "{%0,%1,%2,%3}, {%4,%5,%6,%7}, {%8,%9}, {%0,%1,%2,%3};\n"
                : "+f"(accd[0]), "+f"(accd[1]), "+f"(accd[2]), "+f"(accd[3])
                : "r"(a0), "r"(a1), "r"(a2), "r"(a3), "r"(ONES2), "r"(ONES2));

            // ---- B fragments (x4 per 16-col group) + MMA over all 64 cols ----
            #pragma unroll
            for (int nt2 = 0; nt2 < 4; nt2++) {
                unsigned b0, b1, b2, b3;
                asm volatile("ldmatrix.sync.aligned.m8n8.x4.shared.b16 {%0,%1,%2,%3}, [%4];"
                             : "=r"(b0), "=r"(b1), "=r"(b2), "=r"(b3)
                             : "r"(vBb + nt2 * 16 * 144 + ks * 32));
                asm volatile(
                    "mma.sync.aligned.m16n8k16.row.col.f32.f16.f16.f32 "
                    "{%0,%1,%2,%3}, {%4,%5,%6,%7}, {%8,%9}, {%0,%1,%2,%3};\n"
                    : "+f"(acc[nt2 * 2][0]), "+f"(acc[nt2 * 2][1]),
                      "+f"(acc[nt2 * 2][2]), "+f"(acc[nt2 * 2][3])
                    : "r"(a0), "r"(a1), "r"(a2), "r"(a3), "r"(b0), "r"(b2));
                asm volatile(
                    "mma.sync.aligned.m16n8k16.row.col.f32.f16.f16.f32 "
                    "{%0,%1,%2,%3}, {%4,%5,%6,%7}, {%8,%9}, {%0,%1,%2,%3};\n"
                    : "+f"(acc[nt2 * 2 + 1][0]), "+f"(acc[nt2 * 2 + 1][1]),
                      "+f"(acc[nt2 * 2 + 1][2]), "+f"(acc[nt2 * 2 + 1][3])
                    : "r"(a0), "r"(a1), "r"(a2), "r"(a3), "r"(b1), "r"(b3));
            }
        }
    }

    // ---- denominator write: accd[0]=rowsum(r), accd[2]=rowsum(r+8) ----
    if ((lane & 3) == 0) {
        g_den[(sl * NH + head) * N_NODES + i0 + r]     = accd[0];
        g_den[(sl * NH + head) * N_NODES + i0 + r + 8] = accd[2];
    }

    // ---- numerator slice write ----
    float* nslice = g_num + (size_t)sl * (N_NODES * HID);
    int rr = lane >> 2, cc2 = (lane & 3) * 2;
    #pragma unroll
    for (int nt = 0; nt < 8; nt++) {
        int col  = head * HD + nt * 8 + cc2;
        int row0 = i0 + warp * 16 + rr;
        *(float2*)(nslice + (size_t)row0 * HID + col) =
            make_float2(acc[nt][0], acc[nt][1]);
        *(float2*)(nslice + (size_t)(row0 + 8) * HID + col) =
            make_float2(acc[nt][2], acc[nt][3]);
    }
}

// ---------------- kernel D: combine slices + normalize (float4) -------------
__global__ __launch_bounds__(256) void reduce_norm(float* __restrict__ out) {
    int f = blockIdx.x * 256 + threadIdx.x;      // float4 index
    int i    = f >> 6;
    int c4   = f & 63;
    int head = c4 >> 4;
    const float4* n4 = (const float4*)g_num;
    const size_t SL4 = (size_t)N_NODES * HID / 4;
    float4 A = n4[f], B = n4[SL4 + f], C = n4[2 * SL4 + f], D = n4[3 * SL4 + f];
    int di = head * N_NODES + i;
    const int DN = NH * N_NODES;
    float d = g_den[di] + g_den[DN + di] + g_den[2 * DN + di] + g_den[3 * DN + di];
    float inv = 1.f / d;
    float4 R;
    R.x = (A.x + B.x + C.x + D.x) * inv;
    R.y = (A.y + B.y + C.y + D.y) * inv;
    R.z = (A.z + B.z + C.z + D.z) * inv;
    R.w = (A.w + B.w + C.w + D.w) * inv;
    ((float4*)out)[f] = R;
}

// ---------------- launch ----------------
extern "C" void kernel_launch(void* const* d_in, const int* in_sizes, int n_in,
                              void* d_out, int out_size) {
    const float* x   = (const float*)d_in[0];   // [4096, 256]
    const int*   adj = (const int*)  d_in[1];   // [4096, 4096]
    const float* W   = (const float*)d_in[2];   // [256, 256]
    const float* a1  = (const float*)d_in[3];   // [64]
    const float* a2  = (const float*)d_in[4];   // [64]
    float* out = (float*)d_out;                 // [4096, 256]

    float* h_ptr;
    cudaGetSymbolAddress((void**)&h_ptr, g_h);

    adjpack<<<N_NODES / 8, 256>>>(adj);

    dim3 ggrid(N_NODES / 32, HID / 64);
    gemm_hw<<<ggrid, 256>>>(x, W, h_ptr);

    scores_kernel<<<(N_NODES * NH * 32) / 256, 256>>>(a1, a2);

    attn_mma<<<dim3(N_NODES / TM, NH, NSLICE), 256>>>();

    reduce_norm<<<(N_NODES * HID / 4) / 256, 256>>>(out);
}

// round 16
// speedup vs baseline: 2.6660x; 1.0657x over previous
#include <cuda_runtime.h>
#include <cuda_fp16.h>
#include <math.h>

#define N_NODES 4096
#define IN_F    256
#define NH      4
#define HD      64
#define HID     256   // NH*HD
#define NSLICE  4
#define JSL     (N_NODES / NSLICE)   // 1024 j's per slice
#define TM      128
#define TJ      64
#define NCH     (JSL / TJ)           // 16 chunks per slice

// ---------------- scratch (device globals; no allocs allowed) ----------------
__device__ float    g_h  [N_NODES * HID];               // 4 MB fp32 h = x@W
__device__ __half   g_hT [NH * HD * N_NODES];           // 2 MB fp16 [head*64+d][j]
__device__ float2   g_eip[NH * N_NODES];                // (e^s1, e^{.2 s1})
__device__ float2   g_ejp[NH * N_NODES];                // (e^s2, e^{.2 s2})
__device__ unsigned g_adjb[N_NODES * (N_NODES / 32)];   // 2 MB bit-packed adj
__device__ float    g_num[NSLICE * N_NODES * HID];      // 16 MB numerator slices
__device__ float    g_den[NSLICE * NH * N_NODES];

__device__ __forceinline__ unsigned h2_as_u32(__half2 h) {
    __half2_raw r = *(__half2_raw*)&h;
    return ((unsigned)r.y << 16) | (unsigned)r.x;
}

// ---------------- kernel A0: bit-pack adjacency ------------------------------
__global__ __launch_bounds__(256) void adjpack(const int* __restrict__ adj) {
    int warp = (blockIdx.x * blockDim.x + threadIdx.x) >> 5;   // = row i
    int lane = threadIdx.x & 31;
    const int* row = adj + (size_t)warp * N_NODES;
    unsigned* outw = g_adjb + warp * (N_NODES / 32);
    #pragma unroll 4
    for (int c = 0; c < N_NODES / 32; c++) {
        int v = row[c * 32 + lane];
        unsigned b = __ballot_sync(0xffffffffu, v > 0);
        if (lane == 0) outw[c] = b;
    }
}

// ---------------- kernel A: h = x @ W (32x64 tiles) + fp16-T epilogue --------
__global__ __launch_bounds__(256) void gemm_hw(const float* __restrict__ A,
                                               const float* __restrict__ B,
                                               float* __restrict__ C) {
    __shared__ float As[16][33];
    __shared__ float Bs[16][65];
    __shared__ __half tileh[64 * 40];     // [d][j_local], stride 40
    int tx = threadIdx.x;
    int bm = blockIdx.x * 32;
    int bn = blockIdx.y * 64;             // head = blockIdx.y
    int tm = (tx >> 4) * 2;
    int tn = (tx & 15) * 4;
    float acc[2][4] = {};
    for (int k0 = 0; k0 < 256; k0 += 16) {
        #pragma unroll
        for (int l = 0; l < 2; l++) {
            int idx = tx + l * 256;
            int m = idx >> 4, k = idx & 15;
            As[k][m] = A[(bm + m) * 256 + k0 + k];
        }
        {
            int k = tx >> 6, n = tx & 63;
            #pragma unroll
            for (int l = 0; l < 4; l++)
                Bs[k + l * 4][n] = B[(k0 + k + l * 4) * 256 + bn + n];
        }
        __syncthreads();
        #pragma unroll
        for (int k = 0; k < 16; k++) {
            float a[2], b[4];
            a[0] = As[k][tm]; a[1] = As[k][tm + 1];
            #pragma unroll
            for (int v = 0; v < 4; v++) b[v] = Bs[k][tn + v];
            #pragma unroll
            for (int u = 0; u < 2; u++)
                #pragma unroll
                for (int v = 0; v < 4; v++) acc[u][v] += a[u] * b[v];
        }
        __syncthreads();
    }
    #pragma unroll
    for (int u = 0; u < 2; u++)
        #pragma unroll
        for (int v = 0; v < 4; v++) {
            C[(size_t)(bm + tm + u) * 256 + bn + tn + v] = acc[u][v];
            tileh[(tn + v) * 40 + tm + u] = __float2half_rn(acc[u][v]);
        }
    __syncthreads();
    {
        int drow = tx >> 2, seg = tx & 3;       // 64 d-rows x 4 segs x 8 halves
        uint4 w = *(const uint4*)&tileh[drow * 40 + seg * 8];
        *(uint4*)(g_hT + (size_t)(bn + drow) * N_NODES + bm + seg * 8) = w;
    }
}

// ---------------- kernel B: scores + factorized exponential pairs -----------
__global__ __launch_bounds__(256) void scores_kernel(const float* __restrict__ a1,
                                                     const float* __restrict__ a2) {
    int warp = (blockIdx.x * blockDim.x + threadIdx.x) >> 5;
    int lane = threadIdx.x & 31;
    if (warp >= N_NODES * NH) return;
    int node = warp >> 2, head = warp & 3;
    const float* hp = g_h + node * HID + head * HD;
    float v0 = hp[lane], v1 = hp[lane + 32];
    float s1 = v0 * a1[lane] + v1 * a1[lane + 32];
    float s2 = v0 * a2[lane] + v1 * a2[lane + 32];
    #pragma unroll
    for (int o = 16; o > 0; o >>= 1) {
        s1 += __shfl_xor_sync(0xffffffffu, s1, o);
        s2 += __shfl_xor_sync(0xffffffffu, s2, o);
    }
    if (lane == 0) {
        int idx = head * N_NODES + node;
        g_eip[idx] = make_float2(__expf(s1), __expf(0.2f * s1));
        g_ejp[idx] = make_float2(__expf(s2), __expf(0.2f * s2));
    }
}

// ---------------- kernel C: split-j fp16-MMA, V register-prefetch pipeline --
// w(i,j) = adj ? max(e^si·e^sj, e^{.2si}·e^{.2sj}) : 0; denominator = P @ 1.
__global__ __launch_bounds__(256) void attn_mma() {
    __shared__ float2   esh[JSL];                    // 8 KB (e1j,e2j) pairs
    __shared__ unsigned adjSh[TM * (JSL / 32)];      // 16 KB block's adj slice
    __shared__ __align__(16) __half Vt[2][HD * 72];  // 18 KB double-buffered V

    int t    = threadIdx.x;
    int lane = t & 31;
    int warp = t >> 5;                   // 0..7: owns rows warp*16..+15
    int i0   = blockIdx.x * TM;
    int head = blockIdx.y;
    int sl   = blockIdx.z;
    int jbeg = sl * JSL;

    int gid = lane >> 2, c2 = (lane & 3) * 2;
    int r = warp * 16 + gid;

    int m = t >> 2, q = t & 3;           // V-copy identity (64 d-rows x 4 segs)
    const __half* vsrc = g_hT + (size_t)(head * HD + m) * N_NODES + jbeg + q * 16;

    // ---- prologue: V chunk 0 straight to smem; stage e-pairs + adj slice ----
    {
        uint4 va = *(const uint4*)vsrc;
        uint4 vb = *(const uint4*)(vsrc + 8);
        __half* vd = &Vt[0][m * 72 + q * 16];
        *(uint4*)vd = va;
        *(uint4*)(vd + 8) = vb;
    }
    #pragma unroll
    for (int k = 0; k < 4; k++)
        esh[t + k * 256] = g_ejp[head * N_NODES + jbeg + t + k * 256];
    {
        int rr = t >> 1, seg = t & 1;    // 128 rows x 32 words; 16 words/thread
        const uint4* src = (const uint4*)(g_adjb + (size_t)(i0 + rr) * (N_NODES / 32) + (jbeg >> 5));
        uint4* dst = (uint4*)&adjSh[rr * 32];
        #pragma unroll
        for (int u = 0; u < 4; u++)
            dst[seg * 4 + u] = src[seg * 4 + u];
    }

    float2 eiA = g_eip[head * N_NODES + i0 + r];
    float2 eiB = g_eip[head * N_NODES + i0 + r + 8];
    float acc[8][4];
    #pragma unroll
    for (int a = 0; a < 8; a++)
        #pragma unroll
        for (int b = 0; b < 4; b++) acc[a][b] = 0.f;
    float accd[4] = {0.f, 0.f, 0.f, 0.f};
    const unsigned ONES2 = 0x3C003C00u;  // half2(1,1)

    unsigned vB0;
    {
        unsigned vtb = (unsigned)__cvta_generic_to_shared(&Vt[0][0]);
        vB0 = vtb + ((lane & 7) + ((lane >> 3) & 1) * 8) * 144 + (lane >> 4) * 16;
    }

    __syncthreads();   // V chunk 0 + staging visible

    for (int c = 0; c < NCH; c++) {
        int buf = c & 1;

        // ---- prefetch V chunk c+1 into registers (LDG issued now) ----
        uint4 na, nb;
        if (c + 1 < NCH) {
            const __half* vs = vsrc + (c + 1) * TJ;
            na = *(const uint4*)vs;
            nb = *(const uint4*)(vs + 8);
        }

        // ---- adj words for rows r, r+8 (this 64-j chunk) ----
        uint2 wA = *(const uint2*)&adjSh[r * 32 + c * 2];
        uint2 wB = *(const uint2*)&adjSh[(r + 8) * 32 + c * 2];

        unsigned vBb = vB0 + buf * (HD * 72 * 2);
        const float4* e4 = (const float4*)esh;

        #pragma unroll
        for (int ks = 0; ks < 4; ks++) {
            // ---- build A fragment in registers ----
            float4 eLo = e4[(c * TJ + ks * 16 + c2) >> 1];
            float4 eHi = e4[(c * TJ + ks * 16 + c2 + 8) >> 1];
            unsigned wordA = (ks < 2) ? wA.x : wA.y;
            unsigned wordB = (ks < 2) ? wB.x : wB.y;
            int b = (ks & 1) * 16 + c2;
            float w00 = ((wordA >> b) & 1)       ? fmaxf(eiA.x * eLo.x, eiA.y * eLo.y) : 0.f;
            float w01 = ((wordA >> (b + 1)) & 1) ? fmaxf(eiA.x * eLo.z, eiA.y * eLo.w) : 0.f;
            float w02 = ((wordA >> (b + 8)) & 1) ? fmaxf(eiA.x * eHi.x, eiA.y * eHi.y) : 0.f;
            float w03 = ((wordA >> (b + 9)) & 1) ? fmaxf(eiA.x * eHi.z, eiA.y * eHi.w) : 0.f;
            float w10 = ((wordB >> b) & 1)       ? fmaxf(eiB.x * eLo.x, eiB.y * eLo.y) : 0.f;
            float w11 = ((wordB >> (b + 1)) & 1) ? fmaxf(eiB.x * eLo.z, eiB.y * eLo.w) : 0.f;
            float w12 = ((wordB >> (b + 8)) & 1) ? fmaxf(eiB.x * eHi.x, eiB.y * eHi.y) : 0.f;
            float w13 = ((wordB >> (b + 9)) & 1) ? fmaxf(eiB.x * eHi.z, eiB.y * eHi.w) : 0.f;
            unsigned a0 = h2_as_u32(__floats2half2_rn(w00, w01));
            unsigned a1 = h2_as_u32(__floats2half2_rn(w10, w11));
            unsigned a2 = h2_as_u32(__floats2half2_rn(w02, w03));
            unsigned a3 = h2_as_u32(__floats2half2_rn(w12, w13));

            // ---- denominator: P @ ones via one MMA ----
            asm volatile(
                "mma.sync.aligned.m16n8k16.row.col.f32.f16.f16.f32 "
                "{%0,%1,%2,%3}, {%4,%5,%6,%7}, {%8,%9}, {%0,%1,%2,%3};\n"
                : "+f"(accd[0]), "+f"(accd[1]), "+f"(accd[2]), "+f"(accd[3])
                : "r"(a0), "r"(a1), "r"(a2), "r"(a3), "r"(ONES2), "r"(ONES2));

            // ---- B fragments (x4 per 16-col group) + MMA over all 64 cols ----
            #pragma unroll
            for (int nt2 = 0; nt2 < 4; nt2++) {
                unsigned b0, b1, b2, b3;
                asm volatile("ldmatrix.sync.aligned.m8n8.x4.shared.b16 {%0,%1,%2,%3}, [%4];"
                             : "=r"(b0), "=r"(b1), "=r"(b2), "=r"(b3)
                             : "r"(vBb + nt2 * 16 * 144 + ks * 32));
                asm volatile(
                    "mma.sync.aligned.m16n8k16.row.col.f32.f16.f16.f32 "
                    "{%0,%1,%2,%3}, {%4,%5,%6,%7}, {%8,%9}, {%0,%1,%2,%3};\n"
                    : "+f"(acc[nt2 * 2][0]), "+f"(acc[nt2 * 2][1]),
                      "+f"(acc[nt2 * 2][2]), "+f"(acc[nt2 * 2][3])
                    : "r"(a0), "r"(a1), "r"(a2), "r"(a3), "r"(b0), "r"(b2));
                asm volatile(
                    "mma.sync.aligned.m16n8k16.row.col.f32.f16.f16.f32 "
                    "{%0,%1,%2,%3}, {%4,%5,%6,%7}, {%8,%9}, {%0,%1,%2,%3};\n"
                    : "+f"(acc[nt2 * 2 + 1][0]), "+f"(acc[nt2 * 2 + 1][1]),
                      "+f"(acc[nt2 * 2 + 1][2]), "+f"(acc[nt2 * 2 + 1][3])
                    : "r"(a0), "r"(a1), "r"(a2), "r"(a3), "r"(b1), "r"(b3));
            }
        }

        // ---- store prefetched V into the other buffer; LDG latency hidden ----
        if (c + 1 < NCH) {
            __half* vd = &Vt[buf ^ 1][m * 72 + q * 16];
            *(uint4*)vd = na;
            *(uint4*)(vd + 8) = nb;
        }
        __syncthreads();
    }

    // ---- denominator write: accd[0]=rowsum(r), accd[2]=rowsum(r+8) ----
    if ((lane & 3) == 0) {
        g_den[(sl * NH + head) * N_NODES + i0 + r]     = accd[0];
        g_den[(sl * NH + head) * N_NODES + i0 + r + 8] = accd[2];
    }

    // ---- numerator slice write ----
    float* nslice = g_num + (size_t)sl * (N_NODES * HID);
    int rr = lane >> 2, cc2 = (lane & 3) * 2;
    #pragma unroll
    for (int nt = 0; nt < 8; nt++) {
        int col  = head * HD + nt * 8 + cc2;
        int row0 = i0 + warp * 16 + rr;
        *(float2*)(nslice + (size_t)row0 * HID + col) =
            make_float2(acc[nt][0], acc[nt][1]);
        *(float2*)(nslice + (size_t)(row0 + 8) * HID + col) =
            make_float2(acc[nt][2], acc[nt][3]);
    }
}

// ---------------- kernel D: combine slices + normalize (float4) -------------
__global__ __launch_bounds__(256) void reduce_norm(float* __restrict__ out) {
    int f = blockIdx.x * 256 + threadIdx.x;      // float4 index
    int i    = f >> 6;
    int c4   = f & 63;
    int head = c4 >> 4;
    const float4* n4 = (const float4*)g_num;
    const size_t SL4 = (size_t)N_NODES * HID / 4;
    float4 A = n4[f], B = n4[SL4 + f], C = n4[2 * SL4 + f], D = n4[3 * SL4 + f];
    int di = head * N_NODES + i;
    const int DN = NH * N_NODES;
    float d = g_den[di] + g_den[DN + di] + g_den[2 * DN + di] + g_den[3 * DN + di];
    float inv = 1.f / d;
    float4 R;
    R.x = (A.x + B.x + C.x + D.x) * inv;
    R.y = (A.y + B.y + C.y + D.y) * inv;
    R.z = (A.z + B.z + C.z + D.z) * inv;
    R.w = (A.w + B.w + C.w + D.w) * inv;
    ((float4*)out)[f] = R;
}

// ---------------- launch ----------------
extern "C" void kernel_launch(void* const* d_in, const int* in_sizes, int n_in,
                              void* d_out, int out_size) {
    const float* x   = (const float*)d_in[0];   // [4096, 256]
    const int*   adj = (const int*)  d_in[1];   // [4096, 4096]
    const float* W   = (const float*)d_in[2];   // [256, 256]
    const float* a1  = (const float*)d_in[3];   // [64]
    const float* a2  = (const float*)d_in[4];   // [64]
    float* out = (float*)d_out;                 // [4096, 256]

    float* h_ptr;
    cudaGetSymbolAddress((void**)&h_ptr, g_h);

    adjpack<<<N_NODES / 8, 256>>>(adj);

    dim3 ggrid(N_NODES / 32, HID / 64);
    gemm_hw<<<ggrid, 256>>>(x, W, h_ptr);

    scores_kernel<<<(N_NODES * NH * 32) / 256, 256>>>(a1, a2);

    attn_mma<<<dim3(N_NODES / TM, NH, NSLICE), 256>>>();

    reduce_norm<<<(N_NODES * HID / 4) / 256, 256>>>(out);
}